// round 10
// baseline (speedup 1.0000x reference)
#include <cuda_runtime.h>
#include <cuda_bf16.h>
#include <stdint.h>

// Embedding_44994077393181
// out[b,t,:] = W_emb_tok[ argnz(X[b,t,:]) , : ] + X_emb_pos[t,:]
// X: (2,2048,32000) fp32 one-hot; W: (32000,1024) fp32; pos: (2048,1024) fp32
//
// SINGLE-WARP engine + row pairing.
// One 32-thread CTA handles TWO rows (r, r+2048) sequentially. Per row:
// lock-step-free scan in 2048-float chunks, 16 independent uint4 loads per
// lane per pass (8 KB in flight per warp), integer-OR nonzero detect
// (one-hot bits: 0x0 / 0x3F800000), exit via one __ballot_sync -- zero
// barriers, zero shared memory, zero overshoot. Fused gather + positional
// add (8 float4 per lane). Pairing sums two independent uniform runtimes,
// cutting the end-of-kernel parallelism-decay tail.

#define VOCAB    32000
#define EMB_DIM  1024
#define CTX      2048
#define NROWS    4096         // BATCH * CTX
#define THREADS  32
#define ROWS_PER_CTA 2
#define GRID     (NROWS / ROWS_PER_CTA)
#define CHUNKF4  512          // float4 per pass = 32 lanes * 16  (2048 floats)
#define NPASS    16           // ceil(8000 / 512); last pass partial (320 f4)
#define NQ       8000         // float4 per row

__global__ __launch_bounds__(THREADS)
void embed_onehot_kernel(const float* __restrict__ X,
                         const float* __restrict__ W,
                         const float* __restrict__ pos,
                         float* __restrict__ out)
{
    const int lane = threadIdx.x;

    #pragma unroll 1
    for (int rr = 0; rr < ROWS_PER_CTA; ++rr) {
        const int row = blockIdx.x + rr * GRID;     // rows r and r+2048
        const int t   = row & (CTX - 1);

        const uint4* xv = reinterpret_cast<const uint4*>(X + (size_t)row * VOCAB);

        // ---- scan: find the one-hot index ----
        int idx = -1;

        #pragma unroll 1
        for (int pass = 0; pass < NPASS; ++pass) {
            const int base = pass * CHUNKF4;

            // 16 independent 16B loads per lane (8 KB per warp in flight).
            uint4 v[16];
            #pragma unroll
            for (int j = 0; j < 16; ++j) {
                const int p = base + j * THREADS + lane;
                if (p < NQ) {
                    v[j] = __ldcs(xv + p);
                } else {
                    v[j] = make_uint4(0u, 0u, 0u, 0u);
                }
            }

            // Cheap detect: OR-reduce raw bits (0x0 vs 0x3F800000).
            uint32_t acc = 0u;
            #pragma unroll
            for (int j = 0; j < 16; ++j)
                acc |= (v[j].x | v[j].y) | (v[j].z | v[j].w);

            // Rare path: pinpoint element from live registers.
            int found = -1;
            if (acc != 0u) {
                #pragma unroll
                for (int j = 0; j < 16; ++j) {
                    const int i = (base + j * THREADS + lane) << 2;
                    if (v[j].x) found = i;
                    if (v[j].y) found = i + 1;
                    if (v[j].z) found = i + 2;
                    if (v[j].w) found = i + 3;
                }
            }

            const unsigned m = __ballot_sync(0xffffffffu, found >= 0);
            if (m) {
                const int src = __ffs(m) - 1;       // exactly one lane (one-hot)
                idx = __shfl_sync(0xffffffffu, found, src);
                break;
            }
        }

        // ---- fused gather + positional add: 32 lanes * 8 float4 ----
        const float4* wrow = reinterpret_cast<const float4*>(W   + (size_t)idx * EMB_DIM);
        const float4* prow = reinterpret_cast<const float4*>(pos + (size_t)t   * EMB_DIM);
        float4*       orow = reinterpret_cast<float4*>(out + (size_t)row * EMB_DIM);

        #pragma unroll
        for (int j = 0; j < 8; ++j) {
            const int c = j * THREADS + lane;
            const float4 wv = __ldg(wrow + c);
            const float4 pv = __ldg(prow + c);
            float4 o;
            o.x = wv.x + pv.x;
            o.y = wv.y + pv.y;
            o.z = wv.z + pv.z;
            o.w = wv.w + pv.w;
            orow[c] = o;
        }
    }
}

extern "C" void kernel_launch(void* const* d_in, const int* in_sizes, int n_in,
                              void* d_out, int out_size)
{
    const float* X   = (const float*)d_in[0];   // (2,2048,32000)
    const float* W   = (const float*)d_in[1];   // (32000,1024)
    const float* pos = (const float*)d_in[2];   // (2048,1024)
    float* out = (float*)d_out;                 // (2,2048,1024)

    embed_onehot_kernel<<<GRID, THREADS>>>(X, W, pos, out);
}

// round 11
// speedup vs baseline: 1.0023x; 1.0023x over previous
#include <cuda_runtime.h>
#include <cuda_bf16.h>
#include <stdint.h>

// Embedding_44994077393181
// out[b,t,:] = W_emb_tok[ argnz(X[b,t,:]) , : ] + X_emb_pos[t,:]
// X: (2,2048,32000) fp32 one-hot; W: (32000,1024) fp32; pos: (2048,1024) fp32
//
// R8 engine + SINGLE-WAVE residency.
// One 64-thread CTA (2 warps) per row; lock-step early-exit scan in 2048-float
// chunks, 8 independent uint4 loads/thread/pass, integer-OR detect. Changes vs
// R8: (1) __launch_bounds__(64, 28) caps regs at 36 so all 4096 CTAs are
// resident in ONE wave (R8: 40 regs -> 25 CTAs/SM -> 1.08 waves, forcing ~400
// late-start straggler CTAs). (2) Index recovery re-reads the chunk from L2
// on the rare found path instead of keeping recovery state live in the hot
// loop. (3) Tail guard replaced by a clamp (benign duplicate reads of the
// last float4). Then fused gather + positional add.

#define VOCAB    32000
#define EMB_DIM  1024
#define CTX      2048
#define NROWS    4096         // BATCH * CTX
#define THREADS  64
#define CHUNKF4  512          // float4 per pass = 64 threads * 8  (2048 floats)
#define NPASS    16           // ceil(8000 / 512); last pass clamped
#define NQ       8000         // float4 per row

__global__ __launch_bounds__(THREADS, 28)
void embed_onehot_kernel(const float* __restrict__ X,
                         const float* __restrict__ W,
                         const float* __restrict__ pos,
                         float* __restrict__ out)
{
    const int row = blockIdx.x;            // 0..4095  (b = row / CTX, t = row % CTX)
    const int t   = row & (CTX - 1);
    const int tid = threadIdx.x;

    const uint4* xv = reinterpret_cast<const uint4*>(X + (size_t)row * VOCAB);

    __shared__ int s_idx;

    #pragma unroll 1
    for (int pass = 0; pass < NPASS; ++pass) {
        const int base = pass * CHUNKF4;

        // 8 independent 16B loads per thread (8 KB per CTA in flight).
        // Clamp instead of predicate: duplicate reads of the last float4 are
        // benign (L2 hit; same index recovered if the hit is there).
        uint4 v[8];
        #pragma unroll
        for (int j = 0; j < 8; ++j) {
            int p = base + j * THREADS + tid;
            p = (p < NQ) ? p : (NQ - 1);
            v[j] = __ldcs(xv + p);
        }

        // Cheap detect: OR-reduce raw bits (one-hot: 0x0 / 0x3F800000).
        uint32_t acc = 0u;
        #pragma unroll
        for (int j = 0; j < 8; ++j)
            acc |= (v[j].x | v[j].y) | (v[j].z | v[j].w);

        // Rare path (once per row): re-read from L2 to pinpoint the element,
        // keeping the hot loop's register pressure down.
        int found = -1;
        if (acc != 0u) {
            #pragma unroll 1
            for (int j = 0; j < 8; ++j) {
                int p = base + j * THREADS + tid;
                p = (p < NQ) ? p : (NQ - 1);
                const uint4 w = __ldg(xv + p);
                const int i = p << 2;
                if (w.x) found = i;
                if (w.y) found = i + 1;
                if (w.z) found = i + 2;
                if (w.w) found = i + 3;
            }
            s_idx = found;                 // exactly one nonzero per row
        }

        if (__syncthreads_or(found >= 0)) break;
    }
    __syncthreads();                       // s_idx visible on the break path

    const int idx = s_idx;

    // Fused gather + positional add: 1024 floats = 64 threads * 4 float4.
    const float4* wrow = reinterpret_cast<const float4*>(W   + (size_t)idx * EMB_DIM);
    const float4* prow = reinterpret_cast<const float4*>(pos + (size_t)t   * EMB_DIM);
    float4*       orow = reinterpret_cast<float4*>(out + (size_t)row * EMB_DIM);

    #pragma unroll
    for (int j = 0; j < 4; ++j) {
        const int c = j * THREADS + tid;
        const float4 wv = __ldg(wrow + c);
        const float4 pv = __ldg(prow + c);
        float4 o;
        o.x = wv.x + pv.x;
        o.y = wv.y + pv.y;
        o.z = wv.z + pv.z;
        o.w = wv.w + pv.w;
        orow[c] = o;
    }
}

extern "C" void kernel_launch(void* const* d_in, const int* in_sizes, int n_in,
                              void* d_out, int out_size)
{
    const float* X   = (const float*)d_in[0];   // (2,2048,32000)
    const float* W   = (const float*)d_in[1];   // (32000,1024)
    const float* pos = (const float*)d_in[2];   // (2048,1024)
    float* out = (float*)d_out;                 // (2,2048,1024)

    embed_onehot_kernel<<<NROWS, THREADS>>>(X, W, pos, out);
}

// round 13
// speedup vs baseline: 1.0766x; 1.0741x over previous
#include <cuda_runtime.h>
#include <cuda_bf16.h>
#include <stdint.h>

// Embedding_44994077393181
// out[b,t,:] = W_emb_tok[ argnz(X[b,t,:]) , : ] + X_emb_pos[t,:]
// X: (2,2048,32000) fp32 one-hot; W: (32000,1024) fp32; pos: (2048,1024) fp32
//
// R8 engine (proven best: 64-thread CTA per row, lock-step 2048-float chunks,
// 8 independent uint4 loads/thread/pass, integer-OR detect, in-register index
// recovery) with the per-pass address ALU removed:
//   - thread offset hoisted; one pointer bumped by CHUNKF4 per pass
//   - passes 0..14 are unguarded (15*512 = 7680 < 8000 f4) -> constant-offset
//     LDG.128s issue back-to-back at the LSU floor, compressing the load burst
//   - only the final partial pass (f4 7680..7999) carries bounds guards
// Then fused gather + positional add.
// (Resubmission of R12 -- previous bench attempt died to a container infra
// failure before reaching the GPU.)

#define VOCAB    32000
#define EMB_DIM  1024
#define CTX      2048
#define NROWS    4096         // BATCH * CTX
#define THREADS  64
#define CHUNKF4  512          // float4 per pass = 64 threads * 8  (2048 floats)
#define NFULL    15           // unguarded full passes: 15*512 = 7680 f4
#define NQ       8000         // float4 per row

__global__ __launch_bounds__(THREADS)
void embed_onehot_kernel(const float* __restrict__ X,
                         const float* __restrict__ W,
                         const float* __restrict__ pos,
                         float* __restrict__ out)
{
    const int row = blockIdx.x;            // 0..4095  (b = row / CTX, t = row % CTX)
    const int t   = row & (CTX - 1);
    const int tid = threadIdx.x;

    // Per-thread base pointer: advance by CHUNKF4 each pass; loads then use
    // constant offsets j*THREADS (folded into the LDG immediate).
    const uint4* xp = reinterpret_cast<const uint4*>(X + (size_t)row * VOCAB) + tid;

    __shared__ int s_idx;

    int pass = 0;

    #pragma unroll 1
    for (; pass < NFULL; ++pass) {
        // 8 unguarded, constant-offset 16B loads (8 KB per CTA in flight).
        uint4 v[8];
        #pragma unroll
        for (int j = 0; j < 8; ++j)
            v[j] = __ldcs(xp + j * THREADS);

        // Cheap detect: OR-reduce raw bits (one-hot: 0x0 / 0x3F800000).
        uint32_t acc = 0u;
        #pragma unroll
        for (int j = 0; j < 8; ++j)
            acc |= (v[j].x | v[j].y) | (v[j].z | v[j].w);

        // Rare path (once per row): pinpoint element from live registers.
        int found = -1;
        if (acc != 0u) {
            const int base_i = (pass * CHUNKF4 + tid) << 2;
            #pragma unroll
            for (int j = 0; j < 8; ++j) {
                const int i = base_i + (j * THREADS << 2);
                if (v[j].x) found = i;
                if (v[j].y) found = i + 1;
                if (v[j].z) found = i + 2;
                if (v[j].w) found = i + 3;
            }
            s_idx = found;                 // exactly one nonzero per row
        }

        if (__syncthreads_or(found >= 0)) break;
        xp += CHUNKF4;
    }

    // Final partial pass: f4 slots [7680, 8000), guarded.
    if (pass == NFULL) {
        int found = -1;
        #pragma unroll
        for (int j = 0; j < 8; ++j) {
            const int p = NFULL * CHUNKF4 + j * THREADS + tid;
            if (p < NQ) {
                const uint4 v = __ldcs(xp + j * THREADS);
                if (v.x | v.y | v.z | v.w) {
                    const int i = p << 2;
                    if (v.x) found = i;
                    if (v.y) found = i + 1;
                    if (v.z) found = i + 2;
                    if (v.w) found = i + 3;
                }
            }
        }
        if (found >= 0) s_idx = found;
    }

    __syncthreads();                       // s_idx visible on all exit paths
    const int idx = s_idx;

    // Fused gather + positional add: 1024 floats = 64 threads * 4 float4.
    const float4* wrow = reinterpret_cast<const float4*>(W   + (size_t)idx * EMB_DIM);
    const float4* prow = reinterpret_cast<const float4*>(pos + (size_t)t   * EMB_DIM);
    float4*       orow = reinterpret_cast<float4*>(out + (size_t)row * EMB_DIM);

    #pragma unroll
    for (int j = 0; j < 4; ++j) {
        const int c = j * THREADS + tid;
        const float4 wv = __ldg(wrow + c);
        const float4 pv = __ldg(prow + c);
        float4 o;
        o.x = wv.x + pv.x;
        o.y = wv.y + pv.y;
        o.z = wv.z + pv.z;
        o.w = wv.w + pv.w;
        orow[c] = o;
    }
}

extern "C" void kernel_launch(void* const* d_in, const int* in_sizes, int n_in,
                              void* d_out, int out_size)
{
    const float* X   = (const float*)d_in[0];   // (2,2048,32000)
    const float* W   = (const float*)d_in[1];   // (32000,1024)
    const float* pos = (const float*)d_in[2];   // (2048,1024)
    float* out = (float*)d_out;                 // (2,2048,1024)

    embed_onehot_kernel<<<NROWS, THREADS>>>(X, W, pos, out);
}

// round 14
// speedup vs baseline: 1.0793x; 1.0025x over previous
#include <cuda_runtime.h>
#include <cuda_bf16.h>
#include <stdint.h>

// Embedding_44994077393181
// out[b,t,:] = W_emb_tok[ argnz(X[b,t,:]) , : ] + X_emb_pos[t,:]
// X: (2,2048,32000) fp32 one-hot; W: (32000,1024) fp32; pos: (2048,1024) fp32
//
// Converged engine (R13) + L2 hygiene:
//   - 64-thread CTA per row; lock-step early-exit scan in 2048-float chunks
//   - 8 unguarded constant-offset uint4 loads/thread/pass (pointer-bump,
//     passes 0..14 need no bounds check), integer-OR nonzero detect
//     (one-hot bits: 0x0 / 0x3F800000), in-register index recovery
//   - X streamed with __ldcs (evict-first, zero reuse)
//   - NEW: output written with __stcs (evict-first) so the 17 MB write stream
//     does not evict W rows (~6% duplicate gathers) and pos rows (each read
//     twice: b=0 and b=1) from L2
// Then fused gather + positional add.

#define VOCAB    32000
#define EMB_DIM  1024
#define CTX      2048
#define NROWS    4096         // BATCH * CTX
#define THREADS  64
#define CHUNKF4  512          // float4 per pass = 64 threads * 8  (2048 floats)
#define NFULL    15           // unguarded full passes: 15*512 = 7680 f4
#define NQ       8000         // float4 per row

__global__ __launch_bounds__(THREADS)
void embed_onehot_kernel(const float* __restrict__ X,
                         const float* __restrict__ W,
                         const float* __restrict__ pos,
                         float* __restrict__ out)
{
    const int row = blockIdx.x;            // 0..4095  (b = row / CTX, t = row % CTX)
    const int t   = row & (CTX - 1);
    const int tid = threadIdx.x;

    // Per-thread base pointer: advance by CHUNKF4 each pass; loads then use
    // constant offsets j*THREADS (folded into the LDG immediate).
    const uint4* xp = reinterpret_cast<const uint4*>(X + (size_t)row * VOCAB) + tid;

    __shared__ int s_idx;

    int pass = 0;

    #pragma unroll 1
    for (; pass < NFULL; ++pass) {
        // 8 unguarded, constant-offset 16B loads (8 KB per CTA in flight).
        uint4 v[8];
        #pragma unroll
        for (int j = 0; j < 8; ++j)
            v[j] = __ldcs(xp + j * THREADS);

        // Cheap detect: OR-reduce raw bits (one-hot: 0x0 / 0x3F800000).
        uint32_t acc = 0u;
        #pragma unroll
        for (int j = 0; j < 8; ++j)
            acc |= (v[j].x | v[j].y) | (v[j].z | v[j].w);

        // Rare path (once per row): pinpoint element from live registers.
        int found = -1;
        if (acc != 0u) {
            const int base_i = (pass * CHUNKF4 + tid) << 2;
            #pragma unroll
            for (int j = 0; j < 8; ++j) {
                const int i = base_i + (j * THREADS << 2);
                if (v[j].x) found = i;
                if (v[j].y) found = i + 1;
                if (v[j].z) found = i + 2;
                if (v[j].w) found = i + 3;
            }
            s_idx = found;                 // exactly one nonzero per row
        }

        if (__syncthreads_or(found >= 0)) break;
        xp += CHUNKF4;
    }

    // Final partial pass: f4 slots [7680, 8000), guarded.
    if (pass == NFULL) {
        int found = -1;
        #pragma unroll
        for (int j = 0; j < 8; ++j) {
            const int p = NFULL * CHUNKF4 + j * THREADS + tid;
            if (p < NQ) {
                const uint4 v = __ldcs(xp + j * THREADS);
                if (v.x | v.y | v.z | v.w) {
                    const int i = p << 2;
                    if (v.x) found = i;
                    if (v.y) found = i + 1;
                    if (v.z) found = i + 2;
                    if (v.w) found = i + 3;
                }
            }
        }
        if (found >= 0) s_idx = found;
    }

    __syncthreads();                       // s_idx visible on all exit paths
    const int idx = s_idx;

    // Fused gather + positional add: 1024 floats = 64 threads * 4 float4.
    // Output stored evict-first so the write stream doesn't pollute L2.
    const float4* wrow = reinterpret_cast<const float4*>(W   + (size_t)idx * EMB_DIM);
    const float4* prow = reinterpret_cast<const float4*>(pos + (size_t)t   * EMB_DIM);
    float4*       orow = reinterpret_cast<float4*>(out + (size_t)row * EMB_DIM);

    #pragma unroll
    for (int j = 0; j < 4; ++j) {
        const int c = j * THREADS + tid;
        const float4 wv = __ldg(wrow + c);
        const float4 pv = __ldg(prow + c);
        float4 o;
        o.x = wv.x + pv.x;
        o.y = wv.y + pv.y;
        o.z = wv.z + pv.z;
        o.w = wv.w + pv.w;
        __stcs(orow + c, o);
    }
}

extern "C" void kernel_launch(void* const* d_in, const int* in_sizes, int n_in,
                              void* d_out, int out_size)
{
    const float* X   = (const float*)d_in[0];   // (2,2048,32000)
    const float* W   = (const float*)d_in[1];   // (32000,1024)
    const float* pos = (const float*)d_in[2];   // (2048,1024)
    float* out = (float*)d_out;                 // (2,2048,1024)

    embed_onehot_kernel<<<NROWS, THREADS>>>(X, W, pos, out);
}